// round 2
// baseline (speedup 1.0000x reference)
#include <cuda_runtime.h>
#include <cuda_bf16.h>
#include <math.h>

// Problem constants
#define B_SZ 2
#define S_LEN 2048
#define HID 2048
#define NH 16
#define NKV 4
#define HD 128
#define M_TOK (B_SZ * S_LEN)   // 4096

// ---------------- scratch (device globals: no allocations allowed) ----------
__device__ float g_q[M_TOK * NH * HD];     // (m, 16, 128)
__device__ float g_k[M_TOK * NKV * HD];    // (m, 4, 128)
__device__ float g_v[M_TOK * NKV * HD];
__device__ float g_g1[M_TOK * NH];
__device__ float g_g2[M_TOK * NH];
__device__ float g_att[M_TOK * NH * HD];   // gated+LN'd attention out (m, 2048)
__device__ float g_cosT[S_LEN * 64];
__device__ float g_sinT[S_LEN * 64];

// ---------------- generic SGEMM: C = A(MxK) @ W(KxN), all row-major ---------
// BM=128, BN=128, BK=16, 256 threads, 8x8 per-thread tile
__global__ __launch_bounds__(256) void sgemm128(
    const float* __restrict__ A, const float* __restrict__ W,
    float* __restrict__ C, int M, int N, int K)
{
    __shared__ float As[16][128];
    __shared__ float Bs[16][128];

    const int tid = threadIdx.x;
    const int m0 = blockIdx.y * 128;
    const int n0 = blockIdx.x * 128;
    const int ty = tid >> 4;       // 0..15
    const int tx = tid & 15;       // 0..15

    float acc[8][8];
#pragma unroll
    for (int i = 0; i < 8; i++)
#pragma unroll
        for (int j = 0; j < 8; j++) acc[i][j] = 0.f;

    for (int k0 = 0; k0 < K; k0 += 16) {
        // A tile: 128 rows x 16 cols = 512 float4
#pragma unroll
        for (int t = 0; t < 2; t++) {
            int idx = tid + t * 256;           // 0..511
            int row = idx >> 2;                // 0..127
            int c4  = idx & 3;                 // 0..3
            float4 a = *(const float4*)&A[(size_t)(m0 + row) * K + k0 + c4 * 4];
            As[c4 * 4 + 0][row] = a.x;
            As[c4 * 4 + 1][row] = a.y;
            As[c4 * 4 + 2][row] = a.z;
            As[c4 * 4 + 3][row] = a.w;
        }
        // W tile: 16 rows x 128 cols = 512 float4
#pragma unroll
        for (int t = 0; t < 2; t++) {
            int idx = tid + t * 256;
            int row = idx >> 5;                // 0..15
            int c4  = idx & 31;                // 0..31
            *(float4*)&Bs[row][c4 * 4] =
                *(const float4*)&W[(size_t)(k0 + row) * N + n0 + c4 * 4];
        }
        __syncthreads();

#pragma unroll
        for (int k = 0; k < 16; k++) {
            float a[8], b[8];
            *(float4*)&a[0] = *(float4*)&As[k][ty * 8];
            *(float4*)&a[4] = *(float4*)&As[k][ty * 8 + 4];
            *(float4*)&b[0] = *(float4*)&Bs[k][tx * 8];
            *(float4*)&b[4] = *(float4*)&Bs[k][tx * 8 + 4];
#pragma unroll
            for (int i = 0; i < 8; i++)
#pragma unroll
                for (int j = 0; j < 8; j++)
                    acc[i][j] += a[i] * b[j];
        }
        __syncthreads();
    }

#pragma unroll
    for (int i = 0; i < 8; i++) {
        float4 c0 = make_float4(acc[i][0], acc[i][1], acc[i][2], acc[i][3]);
        float4 c1 = make_float4(acc[i][4], acc[i][5], acc[i][6], acc[i][7]);
        size_t r = (size_t)(m0 + ty * 8 + i) * N + n0 + tx * 8;
        *(float4*)&C[r]     = c0;
        *(float4*)&C[r + 4] = c1;
    }
}

// ---------------- RoPE table (double precision for accurate cos/sin) -------
__global__ void rope_table_kernel(const int* __restrict__ pos,
                                  float* __restrict__ cosT, float* __restrict__ sinT)
{
    int idx = blockIdx.x * blockDim.x + threadIdx.x;
    if (idx >= S_LEN * 64) return;
    int s = idx >> 6, i = idx & 63;
    double p    = (double)pos[s];
    double invf = exp(-((double)i / 64.0) * log(10000.0));
    double ang  = p * invf;
    cosT[idx] = (float)cos(ang);
    sinT[idx] = (float)sin(ang);
}

// ---------------- in-place RoPE on (B*S, heads, 128) ------------------------
__global__ void rope_apply_kernel(float* __restrict__ x,
                                  const float* __restrict__ cosT,
                                  const float* __restrict__ sinT, int heads)
{
    int idx = blockIdx.x * blockDim.x + threadIdx.x;   // B*S*heads*64
    int total = M_TOK * heads * 64;
    if (idx >= total) return;
    int i = idx & 63;
    int h = (idx >> 6) % heads;
    int m = idx / (heads * 64);
    int s = m & (S_LEN - 1);
    float c  = cosT[s * 64 + i];
    float sn = sinT[s * 64 + i];
    float* p = x + ((size_t)m * heads + h) * HD;
    float x0 = p[i], x1 = p[i + 64];
    p[i]      = x0 * c - x1 * sn;
    p[i + 64] = x1 * c + x0 * sn;
}

// ---------------- gates: sigmoid(hidden @ Wg + b), Wg is (2048, 16) ---------
__global__ __launch_bounds__(256) void gates_kernel(
    const float* __restrict__ hidden,
    const float* __restrict__ Wg1, const float* __restrict__ bg1,
    const float* __restrict__ Wg2, const float* __restrict__ bg2,
    float* __restrict__ g1, float* __restrict__ g2)
{
    __shared__ float row[HID];
    int m = blockIdx.x;
    int tid = threadIdx.x;
    for (int c = tid; c < HID / 4; c += 256)
        *(float4*)&row[c * 4] = *(const float4*)&hidden[(size_t)m * HID + c * 4];
    __syncthreads();

    int w = tid >> 5, lane = tid & 31;
    for (int o = w; o < 32; o += 8) {
        int h = o & 15;
        const float* Wg = (o < 16) ? Wg1 : Wg2;
        float s = 0.f;
        for (int k2 = lane; k2 < HID; k2 += 32)
            s += row[k2] * Wg[k2 * NH + h];
#pragma unroll
        for (int off = 16; off; off >>= 1)
            s += __shfl_xor_sync(0xffffffffu, s, off);
        if (lane == 0) {
            float b = (o < 16) ? bg1[h] : bg2[h];
            float val = 1.f / (1.f + __expf(-(s + b)));
            ((o < 16) ? g1 : g2)[(size_t)m * NH + h] = val;
        }
    }
}

// ---------------- flash attention + fused value-gate, LN, output-gate -------
// grid (32 q-tiles, 32 (b,h)); 256 threads; Bq=Bk=64
__global__ __launch_bounds__(256) void flash_kernel(
    const float* __restrict__ Q, const float* __restrict__ Kg,
    const float* __restrict__ Vg,
    const float* __restrict__ g1, const float* __restrict__ g2,
    const float* __restrict__ gamma, const float* __restrict__ beta,
    float* __restrict__ out)
{
    const int qt  = blockIdx.x;
    const int bh  = blockIdx.y;
    const int b   = bh >> 4;
    const int h   = bh & 15;
    const int kvh = h >> 2;
    const int tid = threadIdx.x;
    const int ty  = tid >> 4;     // 0..15 : q-row group
    const int tx  = tid & 15;     // 0..15 : k-col / d-col group

    extern __shared__ float sm[];
    float* Qs  = sm;                 // [64][132]
    float* Ks  = Qs + 64 * 132;
    float* Vs  = Ks + 64 * 132;
    float* Ps  = Vs + 64 * 132;      // [64][68]
    float* r_m = Ps + 64 * 68;       // [64]
    float* r_l = r_m + 64;
    float* r_a = r_l + 64;

    const int q0 = qt * 64;

    // load Q tile (64 x 128)
    for (int idx = tid; idx < 64 * 32; idx += 256) {
        int row = idx >> 5, c4 = idx & 31;
        *(float4*)&Qs[row * 132 + c4 * 4] =
            *(const float4*)&Q[(((size_t)(b * S_LEN + q0 + row)) * NH + h) * HD + c4 * 4];
    }
    if (tid < 64) { r_m[tid] = -1e30f; r_l[tid] = 0.f; }

    float o_acc[4][8];
#pragma unroll
    for (int i = 0; i < 4; i++)
#pragma unroll
        for (int j = 0; j < 8; j++) o_acc[i][j] = 0.f;

    const float scale = 0.08838834764831845f;   // 1/sqrt(128)

    for (int kt = 0; kt <= qt; kt++) {
        const int k0 = kt * 64;
        // load K tile; load V tile with g2 value-gating folded in
        for (int idx = tid; idx < 64 * 32; idx += 256) {
            int row = idx >> 5, c4 = idx & 31;
            size_t tok = (size_t)(b * S_LEN + k0 + row);
            *(float4*)&Ks[row * 132 + c4 * 4] =
                *(const float4*)&Kg[(tok * NKV + kvh) * HD + c4 * 4];
            float gv = g2[tok * NH + h];
            float4 vv = *(const float4*)&Vg[(tok * NKV + kvh) * HD + c4 * 4];
            vv.x *= gv; vv.y *= gv; vv.z *= gv; vv.w *= gv;
            *(float4*)&Vs[row * 132 + c4 * 4] = vv;
        }
        __syncthreads();

        // S = Q K^T (4x4 per thread)
        float s[4][4];
#pragma unroll
        for (int i = 0; i < 4; i++)
#pragma unroll
            for (int j = 0; j < 4; j++) s[i][j] = 0.f;

#pragma unroll 4
        for (int d4 = 0; d4 < 32; d4++) {
            float4 qv[4], kv[4];
#pragma unroll
            for (int i = 0; i < 4; i++)
                qv[i] = *(float4*)&Qs[(ty * 4 + i) * 132 + d4 * 4];
#pragma unroll
            for (int j = 0; j < 4; j++)
                kv[j] = *(float4*)&Ks[(tx * 4 + j) * 132 + d4 * 4];
#pragma unroll
            for (int i = 0; i < 4; i++)
#pragma unroll
                for (int j = 0; j < 4; j++)
                    s[i][j] += qv[i].x * kv[j].x + qv[i].y * kv[j].y +
                               qv[i].z * kv[j].z + qv[i].w * kv[j].w;
        }

        // mask + online softmax per q-row (16 lanes per row, aligned half-warp)
#pragma unroll
        for (int i = 0; i < 4; i++) {
            int row = ty * 4 + i;
            int gq  = q0 + row;
            float sv[4];
            float mx = -1e30f;
#pragma unroll
            for (int j = 0; j < 4; j++) {
                int gk = k0 + tx * 4 + j;
                float x = s[i][j] * scale;
                if (gk > gq) x = -1e30f;
                sv[j] = x;
                mx = fmaxf(mx, x);
            }
#pragma unroll
            for (int off = 8; off; off >>= 1)
                mx = fmaxf(mx, __shfl_xor_sync(0xffffffffu, mx, off));
            float m_old = r_m[row];
            float m_new = fmaxf(m_old, mx);
            float lsum = 0.f;
#pragma unroll
            for (int j = 0; j < 4; j++) {
                float p = __expf(sv[j] - m_new);
                sv[j] = p;
                lsum += p;
            }
#pragma unroll
            for (int off = 8; off; off >>= 1)
                lsum += __shfl_xor_sync(0xffffffffu, lsum, off);
            float alpha = __expf(m_old - m_new);
            if (tx == 0) {
                r_m[row] = m_new;
                r_l[row] = r_l[row] * alpha + lsum;
                r_a[row] = alpha;
            }
#pragma unroll
            for (int j = 0; j < 4; j++)
                Ps[row * 68 + tx * 4 + j] = sv[j];
        }
        __syncthreads();

        // O = O*alpha + P @ V  (thread owns O[ty*4+i][tx*8+j])
        float al[4];
#pragma unroll
        for (int i = 0; i < 4; i++) {
            al[i] = r_a[ty * 4 + i];
#pragma unroll
            for (int j = 0; j < 8; j++) o_acc[i][j] *= al[i];
        }
#pragma unroll 4
        for (int kk = 0; kk < 64; kk++) {
            float p0 = Ps[(ty * 4 + 0) * 68 + kk];
            float p1 = Ps[(ty * 4 + 1) * 68 + kk];
            float p2 = Ps[(ty * 4 + 2) * 68 + kk];
            float p3 = Ps[(ty * 4 + 3) * 68 + kk];
            float4 v0 = *(float4*)&Vs[kk * 132 + tx * 8];
            float4 v1 = *(float4*)&Vs[kk * 132 + tx * 8 + 4];
            float vv[8] = {v0.x, v0.y, v0.z, v0.w, v1.x, v1.y, v1.z, v1.w};
#pragma unroll
            for (int j = 0; j < 8; j++) {
                o_acc[0][j] += p0 * vv[j];
                o_acc[1][j] += p1 * vv[j];
                o_acc[2][j] += p2 * vv[j];
                o_acc[3][j] += p3 * vv[j];
            }
        }
        __syncthreads();
    }

    // epilogue: normalize, per-head LayerNorm over d, g1 gate, store
#pragma unroll
    for (int i = 0; i < 4; i++) {
        int row = ty * 4 + i;
        int gq  = q0 + row;
        float inv_l = 1.f / r_l[row];
        float x[8];
        float sum = 0.f, sumsq = 0.f;
#pragma unroll
        for (int j = 0; j < 8; j++) {
            x[j] = o_acc[i][j] * inv_l;
            sum   += x[j];
            sumsq += x[j] * x[j];
        }
#pragma unroll
        for (int off = 8; off; off >>= 1) {
            sum   += __shfl_xor_sync(0xffffffffu, sum, off);
            sumsq += __shfl_xor_sync(0xffffffffu, sumsq, off);
        }
        float mu   = sum * (1.f / 128.f);
        float var  = sumsq * (1.f / 128.f) - mu * mu;
        float rstd = rsqrtf(var + 1e-5f);
        float gv   = g1[((size_t)(b * S_LEN + gq)) * NH + h];
        size_t base = ((size_t)(b * S_LEN + gq)) * (NH * HD) + h * HD + tx * 8;
#pragma unroll
        for (int j = 0; j < 8; j++) {
            int d = tx * 8 + j;
            float yv = ((x[j] - mu) * rstd * gamma[d] + beta[d]) * gv;
            out[base + j] = yv;
        }
    }
}

// ---------------- launch ----------------------------------------------------
extern "C" void kernel_launch(void* const* d_in, const int* in_sizes, int n_in,
                              void* d_out, int out_size)
{
    const float* hidden = (const float*)d_in[0];
    const int*   pos    = (const int*)d_in[1];
    const float* Wq     = (const float*)d_in[2];
    const float* Wk     = (const float*)d_in[3];
    const float* Wv     = (const float*)d_in[4];
    const float* Wo     = (const float*)d_in[5];
    const float* Wg1    = (const float*)d_in[6];
    const float* bg1    = (const float*)d_in[7];
    const float* Wg2    = (const float*)d_in[8];
    const float* bg2    = (const float*)d_in[9];
    const float* gamma  = (const float*)d_in[10];
    const float* beta   = (const float*)d_in[11];
    float* out = (float*)d_out;

    float *q, *k, *v, *g1, *g2, *att, *cosT, *sinT;
    cudaGetSymbolAddress((void**)&q,    g_q);
    cudaGetSymbolAddress((void**)&k,    g_k);
    cudaGetSymbolAddress((void**)&v,    g_v);
    cudaGetSymbolAddress((void**)&g1,   g_g1);
    cudaGetSymbolAddress((void**)&g2,   g_g2);
    cudaGetSymbolAddress((void**)&att,  g_att);
    cudaGetSymbolAddress((void**)&cosT, g_cosT);
    cudaGetSymbolAddress((void**)&sinT, g_sinT);

    // 1) projections
    sgemm128<<<dim3(16, 32), 256>>>(hidden, Wq, q, M_TOK, NH * HD, HID);
    sgemm128<<<dim3(4, 32), 256>>>(hidden, Wk, k, M_TOK, NKV * HD, HID);
    sgemm128<<<dim3(4, 32), 256>>>(hidden, Wv, v, M_TOK, NKV * HD, HID);

    // 2) RoPE
    rope_table_kernel<<<(S_LEN * 64 + 255) / 256, 256>>>(pos, cosT, sinT);
    rope_apply_kernel<<<(M_TOK * NH * 64) / 256, 256>>>(q, cosT, sinT, NH);
    rope_apply_kernel<<<(M_TOK * NKV * 64) / 256, 256>>>(k, cosT, sinT, NKV);

    // 3) gates
    gates_kernel<<<M_TOK, 256>>>(hidden, Wg1, bg1, Wg2, bg2, g1, g2);

    // 4) flash attention (+fused g2 value-gate, LN, g1 gate)
    size_t smem = (3 * 64 * 132 + 64 * 68 + 3 * 64) * sizeof(float);
    cudaFuncSetAttribute(flash_kernel, cudaFuncAttributeMaxDynamicSharedMemorySize,
                         (int)smem);
    flash_kernel<<<dim3(32, 32), 256, smem>>>(q, k, v, g1, g2, gamma, beta, att);

    // 5) output projection
    sgemm128<<<dim3(16, 32), 256>>>(att, Wo, out, M_TOK, NH * HD, HID);
}

// round 5
// speedup vs baseline: 2.8045x; 2.8045x over previous
#include <cuda_runtime.h>
#include <cuda_bf16.h>
#include <math.h>
#include <stdint.h>

// Problem constants
#define B_SZ 2
#define S_LEN 2048
#define HID 2048
#define NH 16
#define NKV 4
#define HD 128
#define M_TOK (B_SZ * S_LEN)   // 4096

// ---------------- scratch (device globals) ----------------------------------
__device__ float g_q[M_TOK * NH * HD];
__device__ float g_k[M_TOK * NKV * HD];
__device__ float g_v[M_TOK * NKV * HD];
__device__ float g_g1[M_TOK * NH];
__device__ float g_g2[M_TOK * NH];
__device__ float g_att[M_TOK * NH * HD];
__device__ float g_cosT[S_LEN * 64];
__device__ float g_sinT[S_LEN * 64];

// ---------------- tf32 helpers ----------------------------------------------
__device__ __forceinline__ uint32_t f2tf(float f) {
    uint32_t u;
    asm("cvt.rna.tf32.f32 %0, %1;" : "=r"(u) : "f"(f));
    return u;
}

__device__ __forceinline__ void mma8(float c[4], const uint32_t a[4],
                                     uint32_t b0, uint32_t b1) {
    asm volatile(
        "mma.sync.aligned.m16n8k8.row.col.f32.tf32.tf32.f32 "
        "{%0,%1,%2,%3}, {%4,%5,%6,%7}, {%8,%9}, {%0,%1,%2,%3};\n"
        : "+f"(c[0]), "+f"(c[1]), "+f"(c[2]), "+f"(c[3])
        : "r"(a[0]), "r"(a[1]), "r"(a[2]), "r"(a[3]), "r"(b0), "r"(b1));
}

// ---------------- tf32 GEMM: C = A(MxK) @ W(KxN), row-major -----------------
// BM=128 BN=128 BK=16, 256 thr (8 warps, 2x4), warp tile 64x32, mma m16n8k8
__global__ __launch_bounds__(256) void gemm_tf32(
    const float* __restrict__ A, const float* __restrict__ W,
    float* __restrict__ C, int M, int N, int K)
{
    __shared__ uint32_t As[128 * 20];   // [m][k] row-major, stride 20
    __shared__ uint32_t Bs[16 * 136];   // [k][n] row-major, stride 136

    const int tid  = threadIdx.x;
    const int lane = tid & 31;
    const int wid  = tid >> 5;
    const int g    = lane >> 2;   // 0..7
    const int c    = lane & 3;    // 0..3
    const int wm   = (wid >> 2) * 64;
    const int wn   = (wid & 3) * 32;
    const size_t m0 = (size_t)blockIdx.y * 128;
    const size_t n0 = (size_t)blockIdx.x * 128;

    // global-load coords
    const int arow = tid >> 2;          // A rows arow, arow+64 ; col4 = tid&3
    const int ac4  = tid & 3;
    const int brow = tid >> 5;          // B rows brow, brow+8 ; col4 = tid&31
    const int bc4  = tid & 31;

    float acc[4][4][4];
#pragma unroll
    for (int i = 0; i < 4; i++)
#pragma unroll
        for (int j = 0; j < 4; j++)
#pragma unroll
            for (int r = 0; r < 4; r++) acc[i][j][r] = 0.f;

    float4 pa0, pa1, pb0, pb1;

#define GLOAD(k0)                                                              \
    do {                                                                       \
        pa0 = *(const float4*)&A[(m0 + arow)      * K + (k0) + ac4 * 4];       \
        pa1 = *(const float4*)&A[(m0 + arow + 64) * K + (k0) + ac4 * 4];       \
        pb0 = *(const float4*)&W[((size_t)(k0) + brow)     * N + n0 + bc4*4];  \
        pb1 = *(const float4*)&W[((size_t)(k0) + brow + 8) * N + n0 + bc4*4];  \
    } while (0)

#define SSTORE()                                                               \
    do {                                                                       \
        uint4 u;                                                               \
        u.x = f2tf(pa0.x); u.y = f2tf(pa0.y); u.z = f2tf(pa0.z); u.w = f2tf(pa0.w); \
        *(uint4*)&As[arow * 20 + ac4 * 4] = u;                                 \
        u.x = f2tf(pa1.x); u.y = f2tf(pa1.y); u.z = f2tf(pa1.z); u.w = f2tf(pa1.w); \
        *(uint4*)&As[(arow + 64) * 20 + ac4 * 4] = u;                          \
        u.x = f2tf(pb0.x); u.y = f2tf(pb0.y); u.z = f2tf(pb0.z); u.w = f2tf(pb0.w); \
        *(uint4*)&Bs[brow * 136 + bc4 * 4] = u;                                \
        u.x = f2tf(pb1.x); u.y = f2tf(pb1.y); u.z = f2tf(pb1.z); u.w = f2tf(pb1.w); \
        *(uint4*)&Bs[(brow + 8) * 136 + bc4 * 4] = u;                          \
    } while (0)

    GLOAD(0);
    SSTORE();
    __syncthreads();

    for (int k0 = 0; k0 < K; k0 += 16) {
        const bool more = (k0 + 16 < K);
        if (more) GLOAD(k0 + 16);

#pragma unroll
        for (int ks = 0; ks < 2; ks++) {
            const int k = ks * 8;
            uint32_t af[4][4], bf[4][2];
#pragma unroll
            for (int mt = 0; mt < 4; mt++) {
                const uint32_t* ap = &As[(wm + mt * 16 + g) * 20 + k + c];
                af[mt][0] = ap[0];
                af[mt][1] = ap[8 * 20];
                af[mt][2] = ap[4];
                af[mt][3] = ap[8 * 20 + 4];
            }
#pragma unroll
            for (int nt = 0; nt < 4; nt++) {
                const uint32_t* bp = &Bs[(k + c) * 136 + wn + nt * 8 + g];
                bf[nt][0] = bp[0];
                bf[nt][1] = bp[4 * 136];
            }
#pragma unroll
            for (int mt = 0; mt < 4; mt++)
#pragma unroll
                for (int nt = 0; nt < 4; nt++)
                    mma8(acc[mt][nt], af[mt], bf[nt][0], bf[nt][1]);
        }
        __syncthreads();
        if (more) {
            SSTORE();
            __syncthreads();
        }
    }

#pragma unroll
    for (int mt = 0; mt < 4; mt++)
#pragma unroll
        for (int nt = 0; nt < 4; nt++) {
            size_t r  = m0 + wm + mt * 16 + g;
            size_t cc = n0 + wn + nt * 8 + 2 * c;
            *(float2*)&C[r * N + cc]       = make_float2(acc[mt][nt][0], acc[mt][nt][1]);
            *(float2*)&C[(r + 8) * N + cc] = make_float2(acc[mt][nt][2], acc[mt][nt][3]);
        }
#undef GLOAD
#undef SSTORE
}

// ---------------- RoPE table -------------------------------------------------
__global__ void rope_table_kernel(const int* __restrict__ pos,
                                  float* __restrict__ cosT, float* __restrict__ sinT)
{
    int idx = blockIdx.x * blockDim.x + threadIdx.x;
    if (idx >= S_LEN * 64) return;
    int s = idx >> 6, i = idx & 63;
    double p    = (double)pos[s];
    double invf = exp(-((double)i / 64.0) * log(10000.0));
    double ang  = p * invf;
    cosT[idx] = (float)cos(ang);
    sinT[idx] = (float)sin(ang);
}

// ---------------- in-place RoPE ---------------------------------------------
__global__ void rope_apply_kernel(float* __restrict__ x,
                                  const float* __restrict__ cosT,
                                  const float* __restrict__ sinT, int heads)
{
    int idx = blockIdx.x * blockDim.x + threadIdx.x;
    int total = M_TOK * heads * 64;
    if (idx >= total) return;
    int i = idx & 63;
    int h = (idx >> 6) % heads;
    int m = idx / (heads * 64);
    int s = m & (S_LEN - 1);
    float cv = cosT[s * 64 + i];
    float sn = sinT[s * 64 + i];
    float* p = x + ((size_t)m * heads + h) * HD;
    float x0 = p[i], x1 = p[i + 64];
    p[i]      = x0 * cv - x1 * sn;
    p[i + 64] = x1 * cv + x0 * sn;
}

// ---------------- gates ------------------------------------------------------
__global__ __launch_bounds__(256) void gates_kernel(
    const float* __restrict__ hidden,
    const float* __restrict__ Wg1, const float* __restrict__ bg1,
    const float* __restrict__ Wg2, const float* __restrict__ bg2,
    float* __restrict__ g1, float* __restrict__ g2)
{
    __shared__ float row[HID];
    int m = blockIdx.x;
    int tid = threadIdx.x;
    for (int cc = tid; cc < HID / 4; cc += 256)
        *(float4*)&row[cc * 4] = *(const float4*)&hidden[(size_t)m * HID + cc * 4];
    __syncthreads();

    int w = tid >> 5, lane = tid & 31;
    for (int o = w; o < 32; o += 8) {
        int h = o & 15;
        const float* Wg = (o < 16) ? Wg1 : Wg2;
        float s = 0.f;
        for (int k2 = lane; k2 < HID; k2 += 32)
            s += row[k2] * Wg[k2 * NH + h];
#pragma unroll
        for (int off = 16; off; off >>= 1)
            s += __shfl_xor_sync(0xffffffffu, s, off);
        if (lane == 0) {
            float b = (o < 16) ? bg1[h] : bg2[h];
            float val = 1.f / (1.f + __expf(-(s + b)));
            ((o < 16) ? g1 : g2)[(size_t)m * NH + h] = val;
        }
    }
}

// ---------------- tf32 flash attention + fused gates/LN ---------------------
// Bq=128, Bk=64, 256 thr (8 warps); warp w owns q-rows [w*16, w*16+16)
// grid: (S/128, B*NH)
__global__ __launch_bounds__(256) void flash_tf32(
    const float* __restrict__ Q, const float* __restrict__ Kg,
    const float* __restrict__ Vg,
    const float* __restrict__ g1, const float* __restrict__ g2,
    const float* __restrict__ gamma, const float* __restrict__ beta,
    float* __restrict__ out)
{
    const int qt  = blockIdx.x;
    const int bh  = blockIdx.y;
    const int b   = bh >> 4;
    const int h   = bh & 15;
    const int kvh = h >> 2;
    const int tid = threadIdx.x;
    const int lane = tid & 31;
    const int wid  = tid >> 5;
    const int g    = lane >> 2;  // 0..7
    const int c    = lane & 3;   // 0..3
    const int q0   = qt * 128;

    extern __shared__ uint32_t smu[];
    uint32_t* Ks = smu;                 // [64][132]
    uint32_t* Vs = Ks + 64 * 132;       // [64][132]
    uint32_t* PQ = Vs + 64 * 132;       // Q stage [128][132]; later P [128][68]

    const float scale = 0.08838834764831845f;  // 1/sqrt(128)

    // ---- stage Q (scale folded, tf32) ----
    for (int idx = tid; idx < 128 * 32; idx += 256) {
        int row = idx >> 5, c4 = idx & 31;
        float4 qv = *(const float4*)
            &Q[(((size_t)(b * S_LEN + q0 + row)) * NH + h) * HD + c4 * 4];
        uint4 u;
        u.x = f2tf(qv.x * scale); u.y = f2tf(qv.y * scale);
        u.z = f2tf(qv.z * scale); u.w = f2tf(qv.w * scale);
        *(uint4*)&PQ[row * 132 + c4 * 4] = u;
    }
    __syncthreads();

    // ---- extract Q fragments (warp's 16 rows, all 16 k-steps) ----
    uint32_t qf[16][4];
#pragma unroll
    for (int ks = 0; ks < 16; ks++) {
        const uint32_t* qp = &PQ[(wid * 16 + g) * 132 + ks * 8 + c];
        qf[ks][0] = qp[0];
        qf[ks][1] = qp[8 * 132];
        qf[ks][2] = qp[4];
        qf[ks][3] = qp[8 * 132 + 4];
    }
    __syncthreads();   // PQ now reusable as P

    float oacc[16][4];
#pragma unroll
    for (int nt = 0; nt < 16; nt++)
#pragma unroll
        for (int r = 0; r < 4; r++) oacc[nt][r] = 0.f;

    float m_r0 = -1e30f, m_r1 = -1e30f;
    float l_r0 = 0.f,    l_r1 = 0.f;

    const int nkt = 2 * (qt + 1);
    for (int kt = 0; kt < nkt; kt++) {
        const int k0 = kt * 64;

        // ---- load K, V(g2-gated) tiles ----
        for (int idx = tid; idx < 64 * 32; idx += 256) {
            int row = idx >> 5, c4 = idx & 31;
            size_t tok = (size_t)(b * S_LEN + k0 + row);
            float4 kv = *(const float4*)&Kg[(tok * NKV + kvh) * HD + c4 * 4];
            uint4 u;
            u.x = f2tf(kv.x); u.y = f2tf(kv.y); u.z = f2tf(kv.z); u.w = f2tf(kv.w);
            *(uint4*)&Ks[row * 132 + c4 * 4] = u;
            float gv = g2[tok * NH + h];
            float4 vv = *(const float4*)&Vg[(tok * NKV + kvh) * HD + c4 * 4];
            u.x = f2tf(vv.x * gv); u.y = f2tf(vv.y * gv);
            u.z = f2tf(vv.z * gv); u.w = f2tf(vv.w * gv);
            *(uint4*)&Vs[row * 132 + c4 * 4] = u;
        }
        __syncthreads();

        // ---- S = Q K^T : warp computes 16x64 ----
        float s[8][4];
#pragma unroll
        for (int nt = 0; nt < 8; nt++)
#pragma unroll
            for (int r = 0; r < 4; r++) s[nt][r] = 0.f;

#pragma unroll
        for (int ks = 0; ks < 16; ks++) {
#pragma unroll
            for (int nt = 0; nt < 8; nt++) {
                const uint32_t* kp = &Ks[(nt * 8 + g) * 132 + ks * 8 + c];
                mma8(s[nt], qf[ks], kp[0], kp[4]);
            }
        }

        // ---- causal mask (only needed on last two tiles) ----
        if (kt >= 2 * qt) {
            const int r0 = q0 + wid * 16 + g;
            const int r1 = r0 + 8;
#pragma unroll
            for (int nt = 0; nt < 8; nt++) {
                int col = k0 + nt * 8 + 2 * c;
                if (col     > r0) s[nt][0] = -1e30f;
                if (col + 1 > r0) s[nt][1] = -1e30f;
                if (col     > r1) s[nt][2] = -1e30f;
                if (col + 1 > r1) s[nt][3] = -1e30f;
            }
        }

        // ---- online softmax (rows fully owned within 4-lane groups) ----
        float mx0 = -1e30f, mx1 = -1e30f;
#pragma unroll
        for (int nt = 0; nt < 8; nt++) {
            mx0 = fmaxf(mx0, fmaxf(s[nt][0], s[nt][1]));
            mx1 = fmaxf(mx1, fmaxf(s[nt][2], s[nt][3]));
        }
#pragma unroll
        for (int off = 1; off <= 2; off <<= 1) {
            mx0 = fmaxf(mx0, __shfl_xor_sync(0xffffffffu, mx0, off));
            mx1 = fmaxf(mx1, __shfl_xor_sync(0xffffffffu, mx1, off));
        }
        float mn0 = fmaxf(m_r0, mx0), mn1 = fmaxf(m_r1, mx1);
        float sum0 = 0.f, sum1 = 0.f;
#pragma unroll
        for (int nt = 0; nt < 8; nt++) {
            s[nt][0] = __expf(s[nt][0] - mn0);
            s[nt][1] = __expf(s[nt][1] - mn0);
            s[nt][2] = __expf(s[nt][2] - mn1);
            s[nt][3] = __expf(s[nt][3] - mn1);
            sum0 += s[nt][0] + s[nt][1];
            sum1 += s[nt][2] + s[nt][3];
        }
#pragma unroll
        for (int off = 1; off <= 2; off <<= 1) {
            sum0 += __shfl_xor_sync(0xffffffffu, sum0, off);
            sum1 += __shfl_xor_sync(0xffffffffu, sum1, off);
        }
        float a0 = __expf(m_r0 - mn0), a1 = __expf(m_r1 - mn1);
        m_r0 = mn0; m_r1 = mn1;
        l_r0 = l_r0 * a0 + sum0;
        l_r1 = l_r1 * a1 + sum1;
#pragma unroll
        for (int nt = 0; nt < 16; nt++) {
            oacc[nt][0] *= a0; oacc[nt][1] *= a0;
            oacc[nt][2] *= a1; oacc[nt][3] *= a1;
        }

        // ---- store P (warp-private rows) ----
        uint32_t* Ps = PQ;
        {
            const int r0 = wid * 16 + g;
#pragma unroll
            for (int nt = 0; nt < 8; nt++) {
                int col = nt * 8 + 2 * c;
                Ps[r0 * 68 + col]           = f2tf(s[nt][0]);
                Ps[r0 * 68 + col + 1]       = f2tf(s[nt][1]);
                Ps[(r0 + 8) * 68 + col]     = f2tf(s[nt][2]);
                Ps[(r0 + 8) * 68 + col + 1] = f2tf(s[nt][3]);
            }
        }
        __syncwarp();

        // ---- O += P @ V ----
#pragma unroll
        for (int ks = 0; ks < 8; ks++) {
            uint32_t pf[4];
            const uint32_t* pp = &Ps[(wid * 16 + g) * 68 + ks * 8 + c];
            pf[0] = pp[0];
            pf[1] = pp[8 * 68];
            pf[2] = pp[4];
            pf[3] = pp[8 * 68 + 4];
#pragma unroll
            for (int nt = 0; nt < 16; nt++) {
                const uint32_t* vp = &Vs[(ks * 8 + c) * 132 + nt * 8 + g];
                mma8(oacc[nt], pf, vp[0], vp[4 * 132]);
            }
        }
        __syncthreads();
    }

    // ---- stage gamma/beta ----
    float* gb = (float*)Ks;
    if (tid < 128) {
        gb[tid]       = gamma[tid];
        gb[128 + tid] = beta[tid];
    }
    __syncthreads();

    // ---- epilogue: 1/l, LayerNorm over head_dim, g1 gate, store ----
    float inv0 = 1.f / l_r0, inv1 = 1.f / l_r1;
    float su0 = 0.f, sq0 = 0.f, su1 = 0.f, sq1 = 0.f;
#pragma unroll
    for (int nt = 0; nt < 16; nt++) {
        oacc[nt][0] *= inv0; oacc[nt][1] *= inv0;
        oacc[nt][2] *= inv1; oacc[nt][3] *= inv1;
        su0 += oacc[nt][0] + oacc[nt][1];
        sq0 += oacc[nt][0] * oacc[nt][0] + oacc[nt][1] * oacc[nt][1];
        su1 += oacc[nt][2] + oacc[nt][3];
        sq1 += oacc[nt][2] * oacc[nt][2] + oacc[nt][3] * oacc[nt][3];
    }
#pragma unroll
    for (int off = 1; off <= 2; off <<= 1) {
        su0 += __shfl_xor_sync(0xffffffffu, su0, off);
        sq0 += __shfl_xor_sync(0xffffffffu, sq0, off);
        su1 += __shfl_xor_sync(0xffffffffu, su1, off);
        sq1 += __shfl_xor_sync(0xffffffffu, sq1, off);
    }
    float mu0 = su0 * (1.f / 128.f), mu1 = su1 * (1.f / 128.f);
    float rs0 = rsqrtf(sq0 * (1.f / 128.f) - mu0 * mu0 + 1e-5f);
    float rs1 = rsqrtf(sq1 * (1.f / 128.f) - mu1 * mu1 + 1e-5f);

    const int r0 = q0 + wid * 16 + g;
    const int r1 = r0 + 8;
    float gv0 = g1[((size_t)(b * S_LEN + r0)) * NH + h];
    float gv1 = g1[((size_t)(b * S_LEN + r1)) * NH + h];
    size_t base0 = ((size_t)(b * S_LEN + r0)) * (NH * HD) + h * HD;
    size_t base1 = ((size_t)(b * S_LEN + r1)) * (NH * HD) + h * HD;
#pragma unroll
    for (int nt = 0; nt < 16; nt++) {
        int col = nt * 8 + 2 * c;
        float ga = gb[col], gba = gb[128 + col];
        float gc = gb[col + 1], gbc = gb[128 + col + 1];
        float y0 = ((oacc[nt][0] - mu0) * rs0 * ga + gba) * gv0;
        float y1 = ((oacc[nt][1] - mu0) * rs0 * gc + gbc) * gv0;
        float y2 = ((oacc[nt][2] - mu1) * rs1 * ga + gba) * gv1;
        float y3 = ((oacc[nt][3] - mu1) * rs1 * gc + gbc) * gv1;
        *(float2*)&out[base0 + col] = make_float2(y0, y1);
        *(float2*)&out[base1 + col] = make_float2(y2, y3);
    }
}

// ---------------- launch ----------------------------------------------------
extern "C" void kernel_launch(void* const* d_in, const int* in_sizes, int n_in,
                              void* d_out, int out_size)
{
    const float* hidden = (const float*)d_in[0];
    const int*   pos    = (const int*)d_in[1];
    const float* Wq     = (const float*)d_in[2];
    const float* Wk     = (const float*)d_in[3];
    const float* Wv     = (const float*)d_in[4];
    const float* Wo     = (const float*)d_in[5];
    const float* Wg1    = (const float*)d_in[6];
    const float* bg1    = (const float*)d_in[7];
    const float* Wg2    = (const float*)d_in[8];
    const float* bg2    = (const float*)d_in[9];
    const float* gamma  = (const float*)d_in[10];
    const float* beta   = (const float*)d_in[11];
    float* out = (float*)d_out;

    float *q, *k, *v, *g1, *g2, *att, *cosT, *sinT;
    cudaGetSymbolAddress((void**)&q,    g_q);
    cudaGetSymbolAddress((void**)&k,    g_k);
    cudaGetSymbolAddress((void**)&v,    g_v);
    cudaGetSymbolAddress((void**)&g1,   g_g1);
    cudaGetSymbolAddress((void**)&g2,   g_g2);
    cudaGetSymbolAddress((void**)&att,  g_att);
    cudaGetSymbolAddress((void**)&cosT, g_cosT);
    cudaGetSymbolAddress((void**)&sinT, g_sinT);

    // 1) projections (tf32 tensor cores)
    gemm_tf32<<<dim3(16, 32), 256>>>(hidden, Wq, q, M_TOK, NH * HD, HID);
    gemm_tf32<<<dim3(4, 32), 256>>>(hidden, Wk, k, M_TOK, NKV * HD, HID);
    gemm_tf32<<<dim3(4, 32), 256>>>(hidden, Wv, v, M_TOK, NKV * HD, HID);

    // 2) RoPE
    rope_table_kernel<<<(S_LEN * 64 + 255) / 256, 256>>>(pos, cosT, sinT);
    rope_apply_kernel<<<(M_TOK * NH * 64) / 256, 256>>>(q, cosT, sinT, NH);
    rope_apply_kernel<<<(M_TOK * NKV * 64) / 256, 256>>>(k, cosT, sinT, NKV);

    // 3) gates
    gates_kernel<<<M_TOK, 256>>>(hidden, Wg1, bg1, Wg2, bg2, g1, g2);

    // 4) flash attention (tf32 mma, fused g2/LN/g1)
    size_t smem = (size_t)(64 * 132 * 2 + 128 * 132) * 4;   // 135168 B
    cudaFuncSetAttribute(flash_tf32, cudaFuncAttributeMaxDynamicSharedMemorySize,
                         (int)smem);
    flash_tf32<<<dim3(S_LEN / 128, B_SZ * NH), 256, smem>>>(
        q, k, v, g1, g2, gamma, beta, att);

    // 5) output projection
    gemm_tf32<<<dim3(16, 32), 256>>>(att, Wo, out, M_TOK, NH * HD, HID);
}

// round 6
// speedup vs baseline: 2.8233x; 1.0067x over previous
#include <cuda_runtime.h>
#include <cuda_bf16.h>
#include <math.h>
#include <stdint.h>

// Problem constants
#define B_SZ 2
#define S_LEN 2048
#define HID 2048
#define NH 16
#define NKV 4
#define HD 128
#define M_TOK (B_SZ * S_LEN)   // 4096

// ---------------- scratch (device globals) ----------------------------------
__device__ float g_q[M_TOK * NH * HD];
__device__ float g_k[M_TOK * NKV * HD];
__device__ float g_v[M_TOK * NKV * HD];
__device__ float g_g1[M_TOK * NH];
__device__ float g_g2[M_TOK * NH];
__device__ float g_att[M_TOK * NH * HD];
__device__ float g_cosT[S_LEN * 64];
__device__ float g_sinT[S_LEN * 64];

// ---------------- helpers ----------------------------------------------------
__device__ __forceinline__ uint32_t f2tf(float f) {
    uint32_t u;
    asm("cvt.rna.tf32.f32 %0, %1;" : "=r"(u) : "f"(f));
    return u;
}

__device__ __forceinline__ void mma8(float c[4], const uint32_t a[4],
                                     uint32_t b0, uint32_t b1) {
    asm volatile(
        "mma.sync.aligned.m16n8k8.row.col.f32.tf32.tf32.f32 "
        "{%0,%1,%2,%3}, {%4,%5,%6,%7}, {%8,%9}, {%0,%1,%2,%3};\n"
        : "+f"(c[0]), "+f"(c[1]), "+f"(c[2]), "+f"(c[3])
        : "r"(a[0]), "r"(a[1]), "r"(a[2]), "r"(a[3]), "r"(b0), "r"(b1));
}

__device__ __forceinline__ uint32_t smaddr(const void* p) {
    return (uint32_t)__cvta_generic_to_shared(p);
}
#define CP16(dst, src) \
    asm volatile("cp.async.cg.shared.global [%0], [%1], 16;\n" :: "r"(dst), "l"(src))
#define CP4(dst, src)  \
    asm volatile("cp.async.ca.shared.global [%0], [%1], 4;\n"  :: "r"(dst), "l"(src))
#define CPCOMMIT() asm volatile("cp.async.commit_group;\n")
#define CPWAIT0()  asm volatile("cp.async.wait_group 0;\n")
#define CPWAIT1()  asm volatile("cp.async.wait_group 1;\n")

// ---------------- pipelined tf32 GEMM body -----------------------------------
// C = A(Mx2048) @ W(2048xN). BM=128 BN=128 BK=16, 3-stage cp.async.
// stage s: A tile at sm+s*4736 ([128][20] raw f32), B tile at +2560 ([16][136]).
#define GSTG 4736

__device__ __forceinline__ void gemm_issue(
    const float* __restrict__ A, const float* __restrict__ W,
    float* sa, int N, size_t m0, size_t n0, int k0, int tid)
{
    float* sb = sa + 2560;
    {
        int r = tid >> 2, c4 = tid & 3;
        CP16(smaddr(sa + r * 20 + c4 * 4),        A + (m0 + r) * HID + k0 + c4 * 4);
        CP16(smaddr(sa + (r + 64) * 20 + c4 * 4), A + (m0 + r + 64) * HID + k0 + c4 * 4);
    }
    {
        int r = tid >> 5, c4 = tid & 31;
        CP16(smaddr(sb + r * 136 + c4 * 4),       W + (size_t)(k0 + r) * N + n0 + c4 * 4);
        CP16(smaddr(sb + (r + 8) * 136 + c4 * 4), W + (size_t)(k0 + r + 8) * N + n0 + c4 * 4);
    }
}

__device__ __forceinline__ void gemm_body(
    const float* __restrict__ A, const float* __restrict__ W, float* __restrict__ C,
    int N, size_t m0, size_t n0, float* sm)
{
    const int tid  = threadIdx.x;
    const int lane = tid & 31;
    const int wid  = tid >> 5;
    const int g    = lane >> 2;
    const int c    = lane & 3;
    const int wm   = (wid >> 2) * 64;
    const int wn   = (wid & 3) * 32;

    float acc[4][4][4];
#pragma unroll
    for (int i = 0; i < 4; i++)
#pragma unroll
        for (int j = 0; j < 4; j++)
#pragma unroll
            for (int r = 0; r < 4; r++) acc[i][j][r] = 0.f;

    const int NIT = HID / 16;   // 128

    gemm_issue(A, W, sm + 0 * GSTG, N, m0, n0, 0, tid);  CPCOMMIT();
    gemm_issue(A, W, sm + 1 * GSTG, N, m0, n0, 16, tid); CPCOMMIT();

    for (int i = 0; i < NIT; i++) {
        CPWAIT1();
        __syncthreads();
        if (i + 2 < NIT)
            gemm_issue(A, W, sm + ((i + 2) % 3) * GSTG, N, m0, n0, (i + 2) * 16, tid);
        CPCOMMIT();

        const float* sa = sm + (i % 3) * GSTG;
        const float* sb = sa + 2560;
#pragma unroll
        for (int ks = 0; ks < 2; ks++) {
            const int k = ks * 8;
            uint32_t af[4][4], bf[4][2];
#pragma unroll
            for (int mt = 0; mt < 4; mt++) {
                const float* ap = &sa[(wm + mt * 16 + g) * 20 + k + c];
                af[mt][0] = f2tf(ap[0]);
                af[mt][1] = f2tf(ap[8 * 20]);
                af[mt][2] = f2tf(ap[4]);
                af[mt][3] = f2tf(ap[8 * 20 + 4]);
            }
#pragma unroll
            for (int nt = 0; nt < 4; nt++) {
                const float* bp = &sb[(k + c) * 136 + wn + nt * 8 + g];
                bf[nt][0] = f2tf(bp[0]);
                bf[nt][1] = f2tf(bp[4 * 136]);
            }
#pragma unroll
            for (int mt = 0; mt < 4; mt++)
#pragma unroll
                for (int nt = 0; nt < 4; nt++)
                    mma8(acc[mt][nt], af[mt], bf[nt][0], bf[nt][1]);
        }
    }

#pragma unroll
    for (int mt = 0; mt < 4; mt++)
#pragma unroll
        for (int nt = 0; nt < 4; nt++) {
            size_t r  = m0 + wm + mt * 16 + g;
            size_t cc = n0 + wn + nt * 8 + 2 * c;
            *(float2*)&C[r * N + cc]       = make_float2(acc[mt][nt][0], acc[mt][nt][1]);
            *(float2*)&C[(r + 8) * N + cc] = make_float2(acc[mt][nt][2], acc[mt][nt][3]);
        }
}

// fused QKV projections: grid (24, 32)
__global__ __launch_bounds__(256) void qkv_kernel(
    const float* __restrict__ hidden,
    const float* __restrict__ Wq, const float* __restrict__ Wk,
    const float* __restrict__ Wv,
    float* __restrict__ q, float* __restrict__ k, float* __restrict__ v)
{
    extern __shared__ float gsm[];
    int bx = blockIdx.x;
    size_t m0 = (size_t)blockIdx.y * 128;
    if (bx < 16)      gemm_body(hidden, Wq, q, 2048, m0, (size_t)bx * 128, gsm);
    else if (bx < 20) gemm_body(hidden, Wk, k, 512,  m0, (size_t)(bx - 16) * 128, gsm);
    else              gemm_body(hidden, Wv, v, 512,  m0, (size_t)(bx - 20) * 128, gsm);
}

// output projection: grid (16, 32)
__global__ __launch_bounds__(256) void out_kernel(
    const float* __restrict__ att, const float* __restrict__ Wo,
    float* __restrict__ out)
{
    extern __shared__ float gsm[];
    gemm_body(att, Wo, out, 2048, (size_t)blockIdx.y * 128,
              (size_t)blockIdx.x * 128, gsm);
}

// ---------------- RoPE table -------------------------------------------------
__global__ void rope_table_kernel(const int* __restrict__ pos,
                                  float* __restrict__ cosT, float* __restrict__ sinT)
{
    int idx = blockIdx.x * blockDim.x + threadIdx.x;
    if (idx >= S_LEN * 64) return;
    int s = idx >> 6, i = idx & 63;
    double p    = (double)pos[s];
    double invf = exp(-((double)i / 64.0) * log(10000.0));
    double ang  = p * invf;
    cosT[idx] = (float)cos(ang);
    sinT[idx] = (float)sin(ang);
}

// ---------------- in-place RoPE ---------------------------------------------
__global__ void rope_apply_kernel(float* __restrict__ x,
                                  const float* __restrict__ cosT,
                                  const float* __restrict__ sinT, int heads)
{
    int idx = blockIdx.x * blockDim.x + threadIdx.x;
    int total = M_TOK * heads * 64;
    if (idx >= total) return;
    int i = idx & 63;
    int h = (idx >> 6) % heads;
    int m = idx / (heads * 64);
    int s = m & (S_LEN - 1);
    float cv = cosT[s * 64 + i];
    float sn = sinT[s * 64 + i];
    float* p = x + ((size_t)m * heads + h) * HD;
    float x0 = p[i], x1 = p[i + 64];
    p[i]      = x0 * cv - x1 * sn;
    p[i + 64] = x1 * cv + x0 * sn;
}

// ---------------- gates ------------------------------------------------------
__global__ __launch_bounds__(256) void gates_kernel(
    const float* __restrict__ hidden,
    const float* __restrict__ Wg1, const float* __restrict__ bg1,
    const float* __restrict__ Wg2, const float* __restrict__ bg2,
    float* __restrict__ g1, float* __restrict__ g2)
{
    __shared__ float row[HID];
    int m = blockIdx.x;
    int tid = threadIdx.x;
    for (int cc = tid; cc < HID / 4; cc += 256)
        *(float4*)&row[cc * 4] = *(const float4*)&hidden[(size_t)m * HID + cc * 4];
    __syncthreads();

    int w = tid >> 5, lane = tid & 31;
    for (int o = w; o < 32; o += 8) {
        int h = o & 15;
        const float* Wg = (o < 16) ? Wg1 : Wg2;
        float s = 0.f;
        for (int k2 = lane; k2 < HID; k2 += 32)
            s += row[k2] * Wg[k2 * NH + h];
#pragma unroll
        for (int off = 16; off; off >>= 1)
            s += __shfl_xor_sync(0xffffffffu, s, off);
        if (lane == 0) {
            float b = (o < 16) ? bg1[h] : bg2[h];
            float val = 1.f / (1.f + __expf(-(s + b)));
            ((o < 16) ? g1 : g2)[(size_t)m * NH + h] = val;
        }
    }
}

// ---------------- tf32 flash attention (double-buffered) ---------------------
// Bq=128, Bk=64, 256 thr (8 warps); warp w owns q-rows [w*16, w*16+16)
// grid: (S/128, B*NH)
// smem (floats): stage s in {0,1}: K at s*16896, V at s*16896+8448
//   P at 33792 ([128][68]); g2s at 42496 ([2][64]).  total 42624 f = 170496 B
#define KVSTG 16896

__device__ __forceinline__ void kv_issue(
    const float* __restrict__ Kg, const float* __restrict__ Vg,
    const float* __restrict__ g2, float* Kst, float* g2d,
    int base_tok, int kvh, int h, int tid)
{
    float* Vst = Kst + 8448;
#pragma unroll
    for (int t = 0; t < 8; t++) {
        int idx = tid + t * 256;
        int r = idx >> 5, c4 = idx & 31;
        size_t tok = (size_t)(base_tok + r);
        CP16(smaddr(Kst + r * 132 + c4 * 4), Kg + (tok * NKV + kvh) * HD + c4 * 4);
        CP16(smaddr(Vst + r * 132 + c4 * 4), Vg + (tok * NKV + kvh) * HD + c4 * 4);
    }
    if (tid < 64) {
        size_t tok = (size_t)(base_tok + tid);
        CP4(smaddr(g2d + tid), g2 + tok * NH + h);
    }
}

__global__ __launch_bounds__(256) void flash_tf32(
    const float* __restrict__ Q, const float* __restrict__ Kg,
    const float* __restrict__ Vg,
    const float* __restrict__ g1, const float* __restrict__ g2,
    const float* __restrict__ gamma, const float* __restrict__ beta,
    float* __restrict__ out)
{
    const int qt  = blockIdx.x;
    const int bh  = blockIdx.y;
    const int b   = bh >> 4;
    const int h   = bh & 15;
    const int kvh = h >> 2;
    const int tid = threadIdx.x;
    const int lane = tid & 31;
    const int wid  = tid >> 5;
    const int g    = lane >> 2;  // 0..7
    const int c    = lane & 3;   // 0..3
    const int q0   = qt * 128;

    extern __shared__ float smf[];
    float* Ps  = smf + 2 * KVSTG;        // [128][68]
    float* g2s = smf + 2 * KVSTG + 128 * 68;

    const float scale = 0.08838834764831845f;  // 1/sqrt(128)
    const int nkt = 2 * (qt + 1);

    // issue stage 0 while staging Q into stage-1 region
    kv_issue(Kg, Vg, g2, smf, g2s, b * S_LEN, kvh, h, tid);
    CPCOMMIT();

    float* Qst = smf + KVSTG;            // [128][132] raw scaled floats
    for (int idx = tid; idx < 128 * 32; idx += 256) {
        int row = idx >> 5, c4 = idx & 31;
        float4 qv = *(const float4*)
            &Q[(((size_t)(b * S_LEN + q0 + row)) * NH + h) * HD + c4 * 4];
        *(float4*)&Qst[row * 132 + c4 * 4] =
            make_float4(qv.x * scale, qv.y * scale, qv.z * scale, qv.w * scale);
    }
    __syncthreads();

    uint32_t qf[16][4];
#pragma unroll
    for (int ks = 0; ks < 16; ks++) {
        const float* qp = &Qst[(wid * 16 + g) * 132 + ks * 8 + c];
        qf[ks][0] = f2tf(qp[0]);
        qf[ks][1] = f2tf(qp[8 * 132]);
        qf[ks][2] = f2tf(qp[4]);
        qf[ks][3] = f2tf(qp[8 * 132 + 4]);
    }

    float oacc[16][4];
#pragma unroll
    for (int nt = 0; nt < 16; nt++)
#pragma unroll
        for (int r = 0; r < 4; r++) oacc[nt][r] = 0.f;

    float m_r0 = -1e30f, m_r1 = -1e30f;
    float l_r0 = 0.f,    l_r1 = 0.f;

    for (int kt = 0; kt < nkt; kt++) {
        CPWAIT0();
        __syncthreads();
        // issue next tile (overwrites stage computed 2 iters ago / Q staging)
        if (kt + 1 < nkt)
            kv_issue(Kg, Vg, g2, smf + ((kt + 1) & 1) * KVSTG,
                     g2s + ((kt + 1) & 1) * 64,
                     b * S_LEN + (kt + 1) * 64, kvh, h, tid);
        CPCOMMIT();

        const float* Kst = smf + (kt & 1) * KVSTG;
        const float* Vst = Kst + 8448;
        const float* g2p = g2s + (kt & 1) * 64;
        const int k0 = kt * 64;

        // ---- S = Q K^T : warp computes 16x64 ----
        float s[8][4];
#pragma unroll
        for (int nt = 0; nt < 8; nt++)
#pragma unroll
            for (int r = 0; r < 4; r++) s[nt][r] = 0.f;

#pragma unroll
        for (int ks = 0; ks < 16; ks++) {
#pragma unroll
            for (int nt = 0; nt < 8; nt++) {
                const float* kp = &Kst[(nt * 8 + g) * 132 + ks * 8 + c];
                mma8(s[nt], qf[ks], f2tf(kp[0]), f2tf(kp[4]));
            }
        }

        // ---- causal mask (last two tiles only) ----
        if (kt >= 2 * qt) {
            const int r0 = q0 + wid * 16 + g;
            const int r1 = r0 + 8;
#pragma unroll
            for (int nt = 0; nt < 8; nt++) {
                int col = k0 + nt * 8 + 2 * c;
                if (col     > r0) s[nt][0] = -1e30f;
                if (col + 1 > r0) s[nt][1] = -1e30f;
                if (col     > r1) s[nt][2] = -1e30f;
                if (col + 1 > r1) s[nt][3] = -1e30f;
            }
        }

        // ---- online softmax (4-lane row groups) ----
        float mx0 = -1e30f, mx1 = -1e30f;
#pragma unroll
        for (int nt = 0; nt < 8; nt++) {
            mx0 = fmaxf(mx0, fmaxf(s[nt][0], s[nt][1]));
            mx1 = fmaxf(mx1, fmaxf(s[nt][2], s[nt][3]));
        }
#pragma unroll
        for (int off = 1; off <= 2; off <<= 1) {
            mx0 = fmaxf(mx0, __shfl_xor_sync(0xffffffffu, mx0, off));
            mx1 = fmaxf(mx1, __shfl_xor_sync(0xffffffffu, mx1, off));
        }
        float mn0 = fmaxf(m_r0, mx0), mn1 = fmaxf(m_r1, mx1);
        float sum0 = 0.f, sum1 = 0.f;
#pragma unroll
        for (int nt = 0; nt < 8; nt++) {
            s[nt][0] = __expf(s[nt][0] - mn0);
            s[nt][1] = __expf(s[nt][1] - mn0);
            s[nt][2] = __expf(s[nt][2] - mn1);
            s[nt][3] = __expf(s[nt][3] - mn1);
            sum0 += s[nt][0] + s[nt][1];
            sum1 += s[nt][2] + s[nt][3];
        }
#pragma unroll
        for (int off = 1; off <= 2; off <<= 1) {
            sum0 += __shfl_xor_sync(0xffffffffu, sum0, off);
            sum1 += __shfl_xor_sync(0xffffffffu, sum1, off);
        }
        float a0 = __expf(m_r0 - mn0), a1 = __expf(m_r1 - mn1);
        m_r0 = mn0; m_r1 = mn1;
        l_r0 = l_r0 * a0 + sum0;
        l_r1 = l_r1 * a1 + sum1;
#pragma unroll
        for (int nt = 0; nt < 16; nt++) {
            oacc[nt][0] *= a0; oacc[nt][1] *= a0;
            oacc[nt][2] *= a1; oacc[nt][3] *= a1;
        }

        // ---- store P (g2 value-gate folded here; tf32 bits) ----
        {
            const int r0 = wid * 16 + g;
#pragma unroll
            for (int nt = 0; nt < 8; nt++) {
                int col = nt * 8 + 2 * c;
                float w0 = g2p[col], w1 = g2p[col + 1];
                Ps[r0 * 68 + col]           = __uint_as_float(f2tf(s[nt][0] * w0));
                Ps[r0 * 68 + col + 1]       = __uint_as_float(f2tf(s[nt][1] * w1));
                Ps[(r0 + 8) * 68 + col]     = __uint_as_float(f2tf(s[nt][2] * w0));
                Ps[(r0 + 8) * 68 + col + 1] = __uint_as_float(f2tf(s[nt][3] * w1));
            }
        }
        __syncwarp();

        // ---- O += P @ V ----
#pragma unroll
        for (int ks = 0; ks < 8; ks++) {
            uint32_t pf[4];
            const float* pp = &Ps[(wid * 16 + g) * 68 + ks * 8 + c];
            pf[0] = __float_as_uint(pp[0]);
            pf[1] = __float_as_uint(pp[8 * 68]);
            pf[2] = __float_as_uint(pp[4]);
            pf[3] = __float_as_uint(pp[8 * 68 + 4]);
#pragma unroll
            for (int nt = 0; nt < 16; nt++) {
                const float* vp = &Vst[(ks * 8 + c) * 132 + nt * 8 + g];
                mma8(oacc[nt], pf, f2tf(vp[0]), f2tf(vp[4 * 132]));
            }
        }
    }
    __syncthreads();

    // ---- stage gamma/beta ----
    float* gb = smf;
    if (tid < 128) {
        gb[tid]       = gamma[tid];
        gb[128 + tid] = beta[tid];
    }
    __syncthreads();

    // ---- epilogue: 1/l, LayerNorm over head_dim, g1 gate, store ----
    float inv0 = 1.f / l_r0, inv1 = 1.f / l_r1;
    float su0 = 0.f, sq0 = 0.f, su1 = 0.f, sq1 = 0.f;
#pragma unroll
    for (int nt = 0; nt < 16; nt++) {
        oacc[nt][0] *= inv0; oacc[nt][1] *= inv0;
        oacc[nt][2] *= inv1; oacc[nt][3] *= inv1;
        su0 += oacc[nt][0] + oacc[nt][1];
        sq0 += oacc[nt][0] * oacc[nt][0] + oacc[nt][1] * oacc[nt][1];
        su1 += oacc[nt][2] + oacc[nt][3];
        sq1 += oacc[nt][2] * oacc[nt][2] + oacc[nt][3] * oacc[nt][3];
    }
#pragma unroll
    for (int off = 1; off <= 2; off <<= 1) {
        su0 += __shfl_xor_sync(0xffffffffu, su0, off);
        sq0 += __shfl_xor_sync(0xffffffffu, sq0, off);
        su1 += __shfl_xor_sync(0xffffffffu, su1, off);
        sq1 += __shfl_xor_sync(0xffffffffu, sq1, off);
    }
    float mu0 = su0 * (1.f / 128.f), mu1 = su1 * (1.f / 128.f);
    float rs0 = rsqrtf(sq0 * (1.f / 128.f) - mu0 * mu0 + 1e-5f);
    float rs1 = rsqrtf(sq1 * (1.f / 128.f) - mu1 * mu1 + 1e-5f);

    const int r0 = q0 + wid * 16 + g;
    const int r1 = r0 + 8;
    float gv0 = g1[((size_t)(b * S_LEN + r0)) * NH + h];
    float gv1 = g1[((size_t)(b * S_LEN + r1)) * NH + h];
    size_t base0 = ((size_t)(b * S_LEN + r0)) * (NH * HD) + h * HD;
    size_t base1 = ((size_t)(b * S_LEN + r1)) * (NH * HD) + h * HD;
#pragma unroll
    for (int nt = 0; nt < 16; nt++) {
        int col = nt * 8 + 2 * c;
        float ga = gb[col], gba = gb[128 + col];
        float gc = gb[col + 1], gbc = gb[128 + col + 1];
        float y0 = ((oacc[nt][0] - mu0) * rs0 * ga + gba) * gv0;
        float y1 = ((oacc[nt][1] - mu0) * rs0 * gc + gbc) * gv0;
        float y2 = ((oacc[nt][2] - mu1) * rs1 * ga + gba) * gv1;
        float y3 = ((oacc[nt][3] - mu1) * rs1 * gc + gbc) * gv1;
        *(float2*)&out[base0 + col] = make_float2(y0, y1);
        *(float2*)&out[base1 + col] = make_float2(y2, y3);
    }
}

// ---------------- launch ----------------------------------------------------
extern "C" void kernel_launch(void* const* d_in, const int* in_sizes, int n_in,
                              void* d_out, int out_size)
{
    const float* hidden = (const float*)d_in[0];
    const int*   pos    = (const int*)d_in[1];
    const float* Wq     = (const float*)d_in[2];
    const float* Wk     = (const float*)d_in[3];
    const float* Wv     = (const float*)d_in[4];
    const float* Wo     = (const float*)d_in[5];
    const float* Wg1    = (const float*)d_in[6];
    const float* bg1    = (const float*)d_in[7];
    const float* Wg2    = (const float*)d_in[8];
    const float* bg2    = (const float*)d_in[9];
    const float* gamma  = (const float*)d_in[10];
    const float* beta   = (const float*)d_in[11];
    float* out = (float*)d_out;

    float *q, *k, *v, *g1, *g2, *att, *cosT, *sinT;
    cudaGetSymbolAddress((void**)&q,    g_q);
    cudaGetSymbolAddress((void**)&k,    g_k);
    cudaGetSymbolAddress((void**)&v,    g_v);
    cudaGetSymbolAddress((void**)&g1,   g_g1);
    cudaGetSymbolAddress((void**)&g2,   g_g2);
    cudaGetSymbolAddress((void**)&att,  g_att);
    cudaGetSymbolAddress((void**)&cosT, g_cosT);
    cudaGetSymbolAddress((void**)&sinT, g_sinT);

    const int gemm_smem = 3 * GSTG * sizeof(float);   // 56832 B
    cudaFuncSetAttribute(qkv_kernel, cudaFuncAttributeMaxDynamicSharedMemorySize,
                         gemm_smem);
    cudaFuncSetAttribute(out_kernel, cudaFuncAttributeMaxDynamicSharedMemorySize,
                         gemm_smem);

    // 1) fused Q/K/V projections
    qkv_kernel<<<dim3(24, 32), 256, gemm_smem>>>(hidden, Wq, Wk, Wv, q, k, v);

    // 2) RoPE
    rope_table_kernel<<<(S_LEN * 64 + 255) / 256, 256>>>(pos, cosT, sinT);
    rope_apply_kernel<<<(M_TOK * NH * 64) / 256, 256>>>(q, cosT, sinT, NH);
    rope_apply_kernel<<<(M_TOK * NKV * 64) / 256, 256>>>(k, cosT, sinT, NKV);

    // 3) gates
    gates_kernel<<<M_TOK, 256>>>(hidden, Wg1, bg1, Wg2, bg2, g1, g2);

    // 4) flash attention (double-buffered tf32 mma, fused g2/LN/g1)
    const int flash_smem = (2 * KVSTG + 128 * 68 + 2 * 64) * sizeof(float); // 170496
    cudaFuncSetAttribute(flash_tf32, cudaFuncAttributeMaxDynamicSharedMemorySize,
                         flash_smem);
    flash_tf32<<<dim3(S_LEN / 128, B_SZ * NH), 256, flash_smem>>>(
        q, k, v, g1, g2, gamma, beta, att);

    // 5) output projection
    out_kernel<<<dim3(16, 32), 256, gemm_smem>>>(att, Wo, out);
}